// round 17
// baseline (speedup 1.0000x reference)
#include <cuda_runtime.h>
#include <stdint.h>
#include <math.h>

// ---------------------------------------------------------------------------
// UNet forward (B=4, 256x256), NHWC intermediates, tensor-core convs via
// portable mma.sync m16n8k8 tf32 + ldmatrix + cp.async 3-stage pipeline.
// Activations stored pre-rounded to tf32. Graph-capturable; no allocation.
// ---------------------------------------------------------------------------

#define B4 4

// ---------------- workspace buffers (all NHWC: [b][pix][C]) ----------------
__device__ __align__(128) float g_dyn [4*65025*32];
__device__ __align__(128) float g_p1  [4*16384*32];
__device__ __align__(128) float g_t2  [4*16384*128];
__device__ __align__(128) float g_p2  [4*4096*128];
__device__ __align__(128) float g_t3  [4*4096*256];
__device__ __align__(128) float g_p3  [4*1024*256];
__device__ __align__(128) float g_t4  [4*1024*512];
__device__ __align__(128) float g_h4  [4*1024*512];
__device__ __align__(128) float g_cat3[4*4096*768];   // ch[0:512)=up(bn(h4)), [512:768)=c3
__device__ __align__(128) float g_u3t [4*4096*256];
__device__ __align__(128) float g_u3  [4*4096*256];
__device__ __align__(128) float g_cat2[4*16384*384];  // ch[0:256)=up(u3), [256:384)=c2
__device__ __align__(128) float g_u2t [4*16384*128];
__device__ __align__(128) float g_u2  [4*16384*128];
__device__ __align__(128) float g_cat1[4*65536*160];  // ch[0:128)=up(u2), [128:160)=c1
__device__ __align__(128) float g_u1t [4*65536*32];
__device__ __align__(128) float g_u1  [4*65536*32];
__device__ float g_bnscale[512];
__device__ float g_bnshift[512];
__device__ float g_bnp1[32*512];
__device__ float g_bnp2[32*512];
__device__ __align__(16) float g_wt[7700000];   // transposed tf32 weight arena

// Exact identity: tanh(softplus(x)) = t(t+2)/(t(t+2)+2), t = e^x.
__device__ __forceinline__ float mishf(float x) {
    if (x > 15.f) return x;
    float t = __expf(x);
    float u = fmaf(t, t, t + t);
    return x * __fdividef(u, u + 2.f);
}

__device__ __forceinline__ uint32_t to_tf32(float f) {
    uint32_t v;
    asm("cvt.rna.tf32.f32 %0, %1;" : "=r"(v) : "f"(f));
    return v;
}
__device__ __forceinline__ float mish_r(float x) {
    return __uint_as_float(to_tf32(mishf(x)));
}

__device__ __forceinline__ void mma_tf32(float& d0, float& d1, float& d2, float& d3,
                                         uint32_t a0, uint32_t a1, uint32_t a2, uint32_t a3,
                                         uint32_t b0, uint32_t b1) {
    asm volatile("mma.sync.aligned.m16n8k8.row.col.f32.tf32.tf32.f32 "
                 "{%0,%1,%2,%3}, {%4,%5,%6,%7}, {%8,%9}, {%0,%1,%2,%3};"
                 : "+f"(d0), "+f"(d1), "+f"(d2), "+f"(d3)
                 : "r"(a0), "r"(a1), "r"(a2), "r"(a3), "r"(b0), "r"(b1));
}

__device__ __forceinline__ void ldsm_x4(uint32_t& r0, uint32_t& r1, uint32_t& r2, uint32_t& r3,
                                        uint32_t addr) {
    asm volatile("ldmatrix.sync.aligned.m8n8.x4.shared.b16 {%0,%1,%2,%3}, [%4];"
                 : "=r"(r0), "=r"(r1), "=r"(r2), "=r"(r3) : "r"(addr));
}

__device__ __forceinline__ uint32_t smem_u32(const void* p) {
    uint32_t a;
    asm("{ .reg .u64 t; cvta.to.shared.u64 t, %1; cvt.u32.u64 %0, t; }" : "=r"(a) : "l"(p));
    return a;
}

__device__ __forceinline__ void cp_async16(uint32_t dst, const void* src, int src_sz) {
    asm volatile("cp.async.cg.shared.global [%0], [%1], 16, %2;"
                 :: "r"(dst), "l"(src), "r"(src_sz));
}
__device__ __forceinline__ void cp_commit() {
    asm volatile("cp.async.commit_group;" ::: "memory");
}
template<int N>
__device__ __forceinline__ void cp_wait() {
    asm volatile("cp.async.wait_group %0;" :: "n"(N) : "memory");
}

// ---------------------------------------------------------------------------
// Weight transform: w[co][ci][rs] (fp32) -> wt[co][rs][ci] (tf32-rounded fp32)
// ---------------------------------------------------------------------------
__global__ void wtrans_kernel(const float* __restrict__ w, float* __restrict__ o,
                              int Ci, int KK, int total)
{
    int idx = blockIdx.x * blockDim.x + threadIdx.x;
    if (idx >= total) return;
    int cikk = Ci * KK;
    int co = idx / cikk;
    int rem = idx - co * cikk;
    int ci = rem / KK;
    int rs = rem - ci * KK;
    o[(co * KK + rs) * Ci + ci] = __uint_as_float(to_tf32(w[idx]));
}

// ---------------------------------------------------------------------------
// NHWC implicit-GEMM conv: mma.sync tf32, ldmatrix, cp.async 3-stage pipeline.
// Block: BM pixels x BN out-chan, BK=32 (one (r,s), 32 contiguous channels).
// in: [b][Hi*Wi][Ci] (Ci = row stride). out: [b][HoWo][CoutTot] at chan offset.
// Requires Ci%32==0, Co%BN==0, HoWo%BM==0, Ho=Wo=2^logWo.
// ---------------------------------------------------------------------------
template<int K, int PAD, int BM, int BN>
__global__ __launch_bounds__(256)
void conv_mma_kernel(const float* __restrict__ in,
                     const float* __restrict__ wtT,
                     const float* __restrict__ bias,
                     float* __restrict__ outAdj,   // base + channel offset
                     int Ci, int Hi, int Wi,
                     int CoutTot, int logWo, int HoWo)
{
    constexpr int BK = 32;
    constexpr int ST = 3;
    constexpr int SR = BK + 4;
    constexpr int ASZ = BM * SR;
    constexpr int BSZ = BN * SR;
    constexpr int WN = (BN >= 64) ? 2 : 1;
    constexpr int WM = 8 / WN;
    constexpr int WTM = BM / WM;
    constexpr int WTN = BN / WN;
    constexpr int NI = WTN / 8;
    constexpr int NJ = NI / 2;
    constexpr int MMA_M = WTM / 16;
    constexpr int APV = BM / 32;               // A float4 loads per thread (4 or 8)
    constexpr int NB4 = (BN * BK / 4) / 256;

    extern __shared__ float sm[];
    float* As = sm;
    float* Bs = sm + ST * ASZ;
    const uint32_t aBase = smem_u32(As);
    const uint32_t bBase = smem_u32(Bs);

    const int tid = threadIdx.x;
    const int warpId = tid >> 5;
    const int lane = tid & 31;
    const int warpN = (WN == 2) ? (warpId & 1) : 0;
    const int warpM = (WN == 2) ? (warpId >> 1) : warpId;
    const int row = lane >> 2;
    const int colk = lane & 3;

    uint32_t aOff[MMA_M];
#pragma unroll
    for (int mi = 0; mi < MMA_M; mi++)
        aOff[mi] = ((warpM * WTM + mi * 16 + (lane & 15)) * SR + (lane >> 4) * 4) * 4;
    uint32_t bOff[NJ];
#pragma unroll
    for (int nj = 0; nj < NJ; nj++)
        bOff[nj] = ((warpN * WTN + nj * 16 + (lane & 7) + ((lane >> 4) << 3)) * SR
                    + ((lane >> 3) & 1) * 4) * 4;

    const int b = blockIdx.z;
    const int pixBase = blockIdx.x * BM;
    const int coBase = blockIdx.y * BN;
    const int Wo = 1 << logWo;

    const long HiWi = (long)Hi * Wi;
    const float* inB = in + (long)b * HiWi * Ci;
    const int Ktot = K * K * Ci;
    const int KT = Ktot >> 5;

    // ---- A-load thread mapping: pixel pj+32*j, channel chunk k0 ----
    const int pj = tid >> 3;
    const int k0 = (tid & 7) * 4;
    int oyA[APV], oxA[APV];
    const float* pixPtr[APV];
    int okA[APV];
    uint32_t aDstOff[APV];
#pragma unroll
    for (int j = 0; j < APV; j++) {
        int pin = pj + 32 * j;
        int pix = pixBase + pin;
        oyA[j] = pix >> logWo;
        oxA[j] = pix & (Wo - 1);
        pixPtr[j] = inB + ((long)oyA[j] * Wi + oxA[j]) * Ci + k0;
        okA[j] = ((unsigned)(oyA[j] - PAD) < (unsigned)Hi) &&
                 ((unsigned)(oxA[j] - PAD) < (unsigned)Wi) ? 16 : 0;
        aDstOff[j] = (pin * SR + k0) * 4;
    }

    float acc[MMA_M][NI][4];
#pragma unroll
    for (int mi = 0; mi < MMA_M; mi++)
#pragma unroll
        for (int ni = 0; ni < NI; ni++)
#pragma unroll
            for (int i = 0; i < 4; i++) acc[mi][ni][i] = 0.f;

    // ---- incremental (r,s,cB) state ----
    int cB = 0, s_n = 0, r_n = 0;
    long offBase = (-(long)PAD * Wi - PAD) * Ci;

    const float* bPtr[NB4];
    uint32_t bDstOff[NB4];
#pragma unroll
    for (int it = 0; it < NB4; it++) {
        int idx = tid + it * 256;
        int n = idx % BN;
        int kk = (idx / BN) * 4;
        bPtr[it] = wtT + (long)(coBase + n) * Ktot + kk;
        bDstOff[it] = (n * SR + kk) * 4;
    }

    auto issueLoads = [&](int stage) {
        const long srcOff = offBase + cB;
        const uint32_t aDst = aBase + stage * (ASZ * 4);
#pragma unroll
        for (int j = 0; j < APV; j++)
            cp_async16(aDst + aDstOff[j], pixPtr[j] + srcOff, okA[j]);
        const uint32_t bDst = bBase + stage * (BSZ * 4);
#pragma unroll
        for (int it = 0; it < NB4; it++) {
            cp_async16(bDst + bDstOff[it], bPtr[it], 16);
            bPtr[it] += BK;
        }
        cB += BK;
        if (cB == Ci) {
            cB = 0;
            s_n++;
            offBase += Ci;
            if (s_n == K) {
                s_n = 0; r_n++;
                offBase = ((long)(r_n - PAD) * Wi - PAD) * Ci;
            }
#pragma unroll
            for (int j = 0; j < APV; j++) {
                okA[j] = ((unsigned)(oyA[j] + r_n - PAD) < (unsigned)Hi) &&
                         ((unsigned)(oxA[j] + s_n - PAD) < (unsigned)Wi) ? 16 : 0;
            }
        }
    };
    auto compute = [&](int stage) {
        const uint32_t aB = aBase + stage * (ASZ * 4);
        const uint32_t bB = bBase + stage * (BSZ * 4);
#pragma unroll
        for (int ks = 0; ks < 4; ks++) {
            uint32_t af[MMA_M][4];
#pragma unroll
            for (int mi = 0; mi < MMA_M; mi++)
                ldsm_x4(af[mi][0], af[mi][1], af[mi][2], af[mi][3],
                        aB + aOff[mi] + ks * 32);
            uint32_t bf[NI][2];
#pragma unroll
            for (int nj = 0; nj < NJ; nj++) {
                uint32_t r0, r1, r2, r3;
                ldsm_x4(r0, r1, r2, r3, bB + bOff[nj] + ks * 32);
                bf[2 * nj][0] = r0; bf[2 * nj][1] = r1;
                bf[2 * nj + 1][0] = r2; bf[2 * nj + 1][1] = r3;
            }
#pragma unroll
            for (int mi = 0; mi < MMA_M; mi++)
#pragma unroll
                for (int ni = 0; ni < NI; ni++)
                    mma_tf32(acc[mi][ni][0], acc[mi][ni][1], acc[mi][ni][2], acc[mi][ni][3],
                             af[mi][0], af[mi][1], af[mi][2], af[mi][3],
                             bf[ni][0], bf[ni][1]);
        }
    };

#pragma unroll
    for (int s = 0; s < ST - 1; s++) {
        if (s < KT) issueLoads(s);
        cp_commit();
    }

    int stage = 0;
    for (int kt = 0; kt < KT; kt++) {
        cp_wait<ST - 2>();
        __syncthreads();
        if (kt + ST - 1 < KT) issueLoads((stage + ST - 1 >= ST) ? stage - 1 : stage + ST - 1);
        cp_commit();
        compute(stage);
        stage = (stage + 1 == ST) ? 0 : stage + 1;
    }

    // ---- NHWC epilogue: float2 per (pixel, co pair) ----
    float* outB = outAdj + (long)b * HoWo * CoutTot;
#pragma unroll
    for (int mi = 0; mi < MMA_M; mi++) {
#pragma unroll
        for (int ni = 0; ni < NI; ni++) {
            int pixr = pixBase + warpM * WTM + mi * 16 + row;
            int co = coBase + warpN * WTN + ni * 8 + 2 * colk;
            float bi0 = __ldg(bias + co);
            float bi1 = __ldg(bias + co + 1);
            float2 v0, v1;
            v0.x = mish_r(acc[mi][ni][0] + bi0);
            v0.y = mish_r(acc[mi][ni][1] + bi1);
            v1.x = mish_r(acc[mi][ni][2] + bi0);
            v1.y = mish_r(acc[mi][ni][3] + bi1);
            *(float2*)(outB + (long)pixr * CoutTot + co) = v0;
            *(float2*)(outB + (long)(pixr + 8) * CoutTot + co) = v1;
        }
    }
}

// ---------------- dynamic per-sample conv (K=4, pad=1) + mish, NHWC out ----
__global__ void dyn_conv_mish_kernel(const float* __restrict__ x,
                                     const float* __restrict__ w,
                                     float* __restrict__ out)
{
    const int Ho = 255, Wo = 255, Hi = 256, Wi = 256;
    int idx = blockIdx.x * blockDim.x + threadIdx.x;
    int total = 4 * 32 * Ho * Wo;
    if (idx >= total) return;
    int co = idx & 31;
    int t = idx >> 5;
    int pix = t % (Ho * Wo);
    int b = t / (Ho * Wo);
    int oy = pix / Wo, ox = pix - oy * Wo;
    const float* xb = x + b * Hi * Wi;
    const float* wb = w + (b * 32 + co) * 16;
    float acc = 0.f;
#pragma unroll
    for (int ky = 0; ky < 4; ky++) {
        int iy = oy - 1 + ky;
        if (iy < 0 || iy >= Hi) continue;
#pragma unroll
        for (int kx = 0; kx < 4; kx++) {
            int ix = ox - 1 + kx;
            if (ix < 0 || ix >= Wi) continue;
            acc = fmaf(xb[iy * Wi + ix], wb[ky * 4 + kx], acc);
        }
    }
    out[idx] = mish_r(acc);
}

// ---------------- 2x2 maxpool, NHWC (strided-channel input) ----------------
__global__ void maxpool_kernel(const float* __restrict__ in, float* __restrict__ out,
                               int C, int CinTot, int cinOff, int Hi, int Wi)
{
    int Ho = Hi >> 1, Wo = Wi >> 1;
    int idx = blockIdx.x * blockDim.x + threadIdx.x;
    int total = B4 * Ho * Wo * C;
    if (idx >= total) return;
    int c = idx % C;
    int t = idx / C;
    int opix = t % (Ho * Wo);
    int b = t / (Ho * Wo);
    int oy = opix / Wo, ox = opix - oy * Wo;
    const float* p = in + ((long)(b * Hi * Wi) + (2 * oy) * Wi + 2 * ox) * CinTot + cinOff + c;
    float v0 = p[0], v1 = p[CinTot], v2 = p[(long)Wi * CinTot], v3 = p[(long)(Wi + 1) * CinTot];
    out[idx] = fmaxf(fmaxf(v0, v1), fmaxf(v2, v3));
}

// ---------------- batchnorm stats, NHWC, two-stage deterministic ----------
__global__ void bn_part_kernel(const float* __restrict__ h,
                               float* __restrict__ p1, float* __restrict__ p2)
{
    int c = threadIdx.x;          // 512 threads
    int bk = blockIdx.x;          // 32 blocks x 128 pixels
    float s = 0.f, s2 = 0.f;
    const float* base = h + (long)bk * 128 * 512 + c;
    for (int i = 0; i < 128; i++) {
        float v = base[(long)i * 512];
        s += v; s2 += v * v;
    }
    p1[bk * 512 + c] = s;
    p2[bk * 512 + c] = s2;
}
__global__ void bn_final_kernel(const float* __restrict__ p1, const float* __restrict__ p2,
                                const float* __restrict__ g, const float* __restrict__ be,
                                float* __restrict__ scale, float* __restrict__ shift)
{
    int c = blockIdx.x * blockDim.x + threadIdx.x;
    if (c >= 512) return;
    float s = 0.f, s2 = 0.f;
    for (int k = 0; k < 32; k++) { s += p1[k * 512 + c]; s2 += p2[k * 512 + c]; }
    float mean = s * (1.f / 4096.f);
    float var = s2 * (1.f / 4096.f) - mean * mean;
    float sc = g[c] * rsqrtf(var + 1e-5f);
    scale[c] = sc;
    shift[c] = be[c] - mean * sc;
}

// ---------------- bilinear x2 upsample, NHWC, optional BN affine ----------
__global__ void up2_kernel(const float* __restrict__ in, float* __restrict__ outbase,
                           int C, int H, int W, int Ccat,
                           const float* __restrict__ scale,
                           const float* __restrict__ shift)
{
    int Ho = 2 * H, Wo = 2 * W;
    long idx = (long)blockIdx.x * blockDim.x + threadIdx.x;
    long total = (long)B4 * Ho * Wo * C;
    if (idx >= total) return;
    int c = idx % C;
    long t = idx / C;
    int opix = (int)(t % (Ho * Wo));
    int b = (int)(t / (Ho * Wo));
    int oy = opix / Wo, ox = opix - oy * Wo;

    float ry = (float)((double)(H - 1) / (double)(Ho - 1));
    float rx = (float)((double)(W - 1) / (double)(Wo - 1));
    float sy = (float)oy * ry;
    float sx = (float)ox * rx;
    int y0 = (int)floorf(sy);
    int x0 = (int)floorf(sx);
    float fy = sy - (float)y0;
    float fx = sx - (float)x0;
    int y1 = min(y0 + 1, H - 1);
    int x1 = min(x0 + 1, W - 1);

    const float* inB = in + ((long)b * H * W) * C + c;
    float a0 = inB[((long)y0 * W + x0) * C] * (1.f - fy) + inB[((long)y1 * W + x0) * C] * fy;
    float a1 = inB[((long)y0 * W + x1) * C] * (1.f - fy) + inB[((long)y1 * W + x1) * C] * fy;
    float v = a0 * (1.f - fx) + a1 * fx;
    if (scale) v = v * scale[c] + shift[c];
    outbase[((long)(b * Ho * Wo) + opix) * Ccat + c] = __uint_as_float(to_tf32(v));
}

// ---------------- final 1x1 conv (32 -> 1), NHWC in ----------------
__global__ void conv1x1_kernel(const float* __restrict__ in,
                               const float* __restrict__ w,
                               const float* __restrict__ bias,
                               float* __restrict__ out)
{
    int idx = blockIdx.x * blockDim.x + threadIdx.x;
    int total = 4 * 65536;
    if (idx >= total) return;
    const float* p = in + (long)idx * 32;
    float acc = bias[0];
#pragma unroll
    for (int q = 0; q < 8; q++) {
        float4 v = *(const float4*)(p + q * 4);
        acc = fmaf(v.x, w[q * 4 + 0], acc);
        acc = fmaf(v.y, w[q * 4 + 1], acc);
        acc = fmaf(v.z, w[q * 4 + 2], acc);
        acc = fmaf(v.w, w[q * 4 + 3], acc);
    }
    out[idx] = acc;
}

// ---------------------------------------------------------------------------
// Host side
// ---------------------------------------------------------------------------
static float* sym(const void* symbol) {
    void* p = nullptr;
    cudaGetSymbolAddress(&p, symbol);
    return (float*)p;
}

static void wtrans(const float* w, float* dst, int Co, int Ci, int KK) {
    int tot = Co * Ci * KK;
    wtrans_kernel<<<(tot + 255) / 256, 256>>>(w, dst, Ci, KK, tot);
}

template<int K, int PAD, int BM, int BN>
static void conv_mma(const float* in, const float* wtT, const float* bs,
                     float* out, int coutOff,
                     int Ci, int Hi, int Wi, int Co, int CoutTot, int logWo)
{
    const int HoWo = 1 << (2 * logWo);
    const size_t smem = (3 * (size_t)BM * 36 + 3 * (size_t)BN * 36) * sizeof(float);
    cudaFuncSetAttribute(conv_mma_kernel<K, PAD, BM, BN>,
                         cudaFuncAttributeMaxDynamicSharedMemorySize, (int)smem);
    dim3 g(HoWo / BM, Co / BN, B4);
    conv_mma_kernel<K, PAD, BM, BN><<<g, 256, smem>>>(in, wtT, bs,
        out + coutOff, Ci, Hi, Wi, CoutTot, logWo, HoWo);
}

// weight arena offsets (floats)
#define O_D1  0L
#define O_W2A (O_D1  + 32L*32*16)
#define O_W2B (O_W2A + 128L*32*9)
#define O_W3A (O_W2B + 128L*128*9)
#define O_W3B (O_W3A + 256L*128*9)
#define O_W4A (O_W3B + 256L*256*9)
#define O_W4B (O_W4A + 512L*256*9)
#define O_U3A (O_W4B + 512L*512*9)
#define O_U3B (O_U3A + 256L*768*9)
#define O_U2A (O_U3B + 256L*256*9)
#define O_U2B (O_U2A + 128L*384*9)
#define O_U1A (O_U2B + 128L*128*9)
#define O_U1B (O_U1A + 32L*160*9)

extern "C" void kernel_launch(void* const* d_in, const int* in_sizes, int n_in,
                              void* d_out, int out_size)
{
    const float* x   = (const float*)d_in[0];
    const float* w   = (const float*)d_in[1];
    const float* d1w = (const float*)d_in[2];
    const float* d1b = (const float*)d_in[3];
    const float* w2a = (const float*)d_in[4];
    const float* b2a = (const float*)d_in[5];
    const float* w2b = (const float*)d_in[6];
    const float* b2b = (const float*)d_in[7];
    const float* w3a = (const float*)d_in[8];
    const float* b3a = (const float*)d_in[9];
    const float* w3b = (const float*)d_in[10];
    const float* b3b = (const float*)d_in[11];
    const float* w4a = (const float*)d_in[12];
    const float* b4a = (const float*)d_in[13];
    const float* w4b = (const float*)d_in[14];
    const float* b4b = (const float*)d_in[15];
    const float* g4  = (const float*)d_in[16];
    const float* be4 = (const float*)d_in[17];
    const float* u3a = (const float*)d_in[18];
    const float* ub3a= (const float*)d_in[19];
    const float* u3b = (const float*)d_in[20];
    const float* ub3b= (const float*)d_in[21];
    const float* u2a = (const float*)d_in[22];
    const float* ub2a= (const float*)d_in[23];
    const float* u2b = (const float*)d_in[24];
    const float* ub2b= (const float*)d_in[25];
    const float* u1a = (const float*)d_in[26];
    const float* ub1a= (const float*)d_in[27];
    const float* u1b = (const float*)d_in[28];
    const float* ub1b= (const float*)d_in[29];
    const float* wl  = (const float*)d_in[30];
    const float* bl  = (const float*)d_in[31];
    float* out = (float*)d_out;

    float* dyn  = sym(g_dyn);
    float* p1   = sym(g_p1);
    float* t2   = sym(g_t2);
    float* p2   = sym(g_p2);
    float* t3   = sym(g_t3);
    float* p3   = sym(g_p3);
    float* t4   = sym(g_t4);
    float* h4   = sym(g_h4);
    float* cat3 = sym(g_cat3);
    float* u3t  = sym(g_u3t);
    float* u3   = sym(g_u3);
    float* cat2 = sym(g_cat2);
    float* u2t  = sym(g_u2t);
    float* u2   = sym(g_u2);
    float* cat1 = sym(g_cat1);
    float* u1t  = sym(g_u1t);
    float* u1   = sym(g_u1);
    float* bnsc = sym(g_bnscale);
    float* bnsh = sym(g_bnshift);
    float* bnp1 = sym(g_bnp1);
    float* bnp2 = sym(g_bnp2);
    float* wa   = sym(g_wt);

    // 0. all weight transforms up-front
    wtrans(d1w, wa + O_D1,  32,  32, 16);
    wtrans(w2a, wa + O_W2A, 128, 32,  9);
    wtrans(w2b, wa + O_W2B, 128, 128, 9);
    wtrans(w3a, wa + O_W3A, 256, 128, 9);
    wtrans(w3b, wa + O_W3B, 256, 256, 9);
    wtrans(w4a, wa + O_W4A, 512, 256, 9);
    wtrans(w4b, wa + O_W4B, 512, 512, 9);
    wtrans(u3a, wa + O_U3A, 256, 768, 9);
    wtrans(u3b, wa + O_U3B, 256, 256, 9);
    wtrans(u2a, wa + O_U2A, 128, 384, 9);
    wtrans(u2b, wa + O_U2B, 128, 128, 9);
    wtrans(u1a, wa + O_U1A, 32,  160, 9);
    wtrans(u1b, wa + O_U1B, 32,  32,  9);

    // 1. dynamic conv + mish : NHWC (4,65025,32)
    {
        int total = 4 * 65025 * 32;
        dyn_conv_mish_kernel<<<(total + 255) / 256, 256>>>(x, w, dyn);
    }
    // 2. d1 conv (K=4, pad=2): c1 -> cat1 ch[128:160] @ 256x256
    conv_mma<4, 2, 256, 32>(dyn, wa + O_D1, d1b, cat1, 128, 32, 255, 255, 32, 160, 8);
    // 3. pool c1 -> p1 (4,16384,32)
    {
        int total = 4 * 16384 * 32;
        maxpool_kernel<<<(total + 255) / 256, 256>>>(cat1, p1, 32, 160, 128, 256, 256);
    }
    // 4-5. double conv 2 : c2 -> cat2 ch[256:384] @ 128x128
    conv_mma<3, 1, 128, 128>(p1, wa + O_W2A, b2a, t2, 0, 32, 128, 128, 128, 128, 7);
    conv_mma<3, 1, 128, 128>(t2, wa + O_W2B, b2b, cat2, 256, 128, 128, 128, 128, 384, 7);
    // 6. pool c2 -> p2 (4,4096,128)
    {
        int total = 4 * 4096 * 128;
        maxpool_kernel<<<(total + 255) / 256, 256>>>(cat2, p2, 128, 384, 256, 128, 128);
    }
    // 7-8. double conv 3 : c3 -> cat3 ch[512:768] @ 64x64
    conv_mma<3, 1, 128, 128>(p2, wa + O_W3A, b3a, t3, 0, 128, 64, 64, 256, 256, 6);
    conv_mma<3, 1, 128, 128>(t3, wa + O_W3B, b3b, cat3, 512, 256, 64, 64, 256, 768, 6);
    // 9. pool c3 -> p3 (4,1024,256)
    {
        int total = 4 * 1024 * 256;
        maxpool_kernel<<<(total + 255) / 256, 256>>>(cat3, p3, 256, 768, 512, 64, 64);
    }
    // 10-11. double conv 4 : (4,1024,512)
    conv_mma<3, 1, 128, 64>(p3, wa + O_W4A, b4a, t4, 0, 256, 32, 32, 512, 512, 5);
    conv_mma<3, 1, 128, 64>(t4, wa + O_W4B, b4b, h4, 0, 512, 32, 32, 512, 512, 5);
    // 12. batchnorm stats (two-stage, deterministic)
    bn_part_kernel<<<32, 512>>>(h4, bnp1, bnp2);
    bn_final_kernel<<<2, 256>>>(bnp1, bnp2, g4, be4, bnsc, bnsh);
    // 13. upsample(bn(h4)) -> cat3 ch[0:512] @ 64x64
    {
        long total = (long)4 * 4096 * 512;
        up2_kernel<<<(int)((total + 255) / 256), 256>>>(h4, cat3, 512, 32, 32, 768, bnsc, bnsh);
    }
    // 14-15. double conv u3 : (4,4096,256)
    conv_mma<3, 1, 128, 128>(cat3, wa + O_U3A, ub3a, u3t, 0, 768, 64, 64, 256, 256, 6);
    conv_mma<3, 1, 128, 128>(u3t, wa + O_U3B, ub3b, u3, 0, 256, 64, 64, 256, 256, 6);
    // 16. upsample u3 -> cat2 ch[0:256] @ 128x128
    {
        long total = (long)4 * 16384 * 256;
        up2_kernel<<<(int)((total + 255) / 256), 256>>>(u3, cat2, 256, 64, 64, 384, nullptr, nullptr);
    }
    // 17-18. double conv u2 : (4,16384,128)
    conv_mma<3, 1, 128, 128>(cat2, wa + O_U2A, ub2a, u2t, 0, 384, 128, 128, 128, 128, 7);
    conv_mma<3, 1, 128, 128>(u2t, wa + O_U2B, ub2b, u2, 0, 128, 128, 128, 128, 128, 7);
    // 19. upsample u2 -> cat1 ch[0:128] @ 256x256
    {
        long total = (long)4 * 65536 * 128;
        up2_kernel<<<(int)((total + 255) / 256), 256>>>(u2, cat1, 128, 128, 128, 160, nullptr, nullptr);
    }
    // 20-21. double conv u1 : (4,65536,32)
    conv_mma<3, 1, 256, 32>(cat1, wa + O_U1A, ub1a, u1t, 0, 160, 256, 256, 32, 32, 8);
    conv_mma<3, 1, 256, 32>(u1t, wa + O_U1B, ub1b, u1, 0, 32, 256, 256, 32, 32, 8);
    // 22. final 1x1 conv -> (4,1,256,256)
    {
        int total = 4 * 65536;
        conv1x1_kernel<<<(total + 255) / 256, 256>>>(u1, wl, bl, out);
    }
}